// round 3
// baseline (speedup 1.0000x reference)
#include <cuda_runtime.h>
#include <math.h>

// Problem constants
constexpr int D  = 1024;   // d_model
constexpr int B  = 1024;   // queries
constexpr int N  = 16384;  // candidates
constexpr int H  = 8;      // heads
constexpr int HD = 128;    // head dim
constexpr int BCHUNK = 128;            // query rows per scores chunk
constexpr int NCHUNKS = B / BCHUNK;    // 8

// ---------------------------------------------------------------------------
// Scratch (static device arrays — ~260 MB total; no runtime allocation)
// g_tmp: k-projection intermediate, later reused to hold kh.
// ---------------------------------------------------------------------------
__device__ float g_tmp [(size_t)N * D];          // 64 MB
__device__ float g_kp  [(size_t)N * D];          // 64 MB
__device__ float g_qtmp[(size_t)B * D];          // 4 MB
__device__ float g_qp  [(size_t)B * D];          // 4 MB
__device__ float g_qh  [(size_t)B * D];          // 4 MB
__device__ float g_dot [(size_t)B * N];          // 64 MB
__device__ float g_sc  [(size_t)BCHUNK * H * N]; // 64 MB (one chunk of scores)
__device__ float g_qsq[B];
__device__ float g_ksq[N];
__device__ float g_mx [BCHUNK * H];
__device__ float g_rs [BCHUNK * H];

// ---------------------------------------------------------------------------
// Generic tiled SGEMM: C[M,NN] = alpha * A @ B (+ bias), optional B-transpose.
// BM=BN=128, BK=16, 256 threads, 8x8 per-thread microtile.
// Requires: M%128==0, NN%128==0, K%16==0, strides %4==0. (All true here.)
// When BATCH_HEADS: blockIdx.z = head h; A += h*HD, B += h*HD, C += h*N.
// ---------------------------------------------------------------------------
constexpr int BM = 128, BN = 128, BK = 16, TM = 8, TN = 8;

template <bool TRANSB, bool BATCH_HEADS>
__global__ void __launch_bounds__(256)
gemm_kernel(const float* __restrict__ A, const float* __restrict__ Bm,
            const float* __restrict__ bias, float* __restrict__ C,
            int M, int NN, int K, int lda, int ldb, int ldc, float alpha)
{
    __shared__ float As[BK][BM];
    __shared__ float Bs[BK][BN];

    if (BATCH_HEADS) {
        const int h = blockIdx.z;
        A += (size_t)h * HD;
        Bm += (size_t)h * HD;
        C += (size_t)h * N;
    }

    const int tid = threadIdx.x;
    const int m0 = blockIdx.y * BM;
    const int n0 = blockIdx.x * BN;
    const int tx = tid & 15;   // 0..15
    const int ty = tid >> 4;   // 0..15

    float acc[TM][TN];
#pragma unroll
    for (int i = 0; i < TM; i++)
#pragma unroll
        for (int j = 0; j < TN; j++) acc[i][j] = 0.f;

    for (int k0 = 0; k0 < K; k0 += BK) {
        // Load A tile [BM x BK], store transposed into As[k][m]
#pragma unroll
        for (int s = 0; s < 2; s++) {
            int slot = tid + s * 256;          // 0..511
            int row  = slot >> 2;              // 0..127
            int kc   = (slot & 3) * 4;         // 0,4,8,12
            float4 v = *reinterpret_cast<const float4*>(
                &A[(size_t)(m0 + row) * lda + k0 + kc]);
            As[kc + 0][row] = v.x; As[kc + 1][row] = v.y;
            As[kc + 2][row] = v.z; As[kc + 3][row] = v.w;
        }
        if (TRANSB) {
            // B is [NN x K] row-major: tile rows n0..n0+127, cols k0..k0+15
#pragma unroll
            for (int s = 0; s < 2; s++) {
                int slot = tid + s * 256;
                int row  = slot >> 2;
                int kc   = (slot & 3) * 4;
                float4 v = *reinterpret_cast<const float4*>(
                    &Bm[(size_t)(n0 + row) * ldb + k0 + kc]);
                Bs[kc + 0][row] = v.x; Bs[kc + 1][row] = v.y;
                Bs[kc + 2][row] = v.z; Bs[kc + 3][row] = v.w;
            }
        } else {
            // B is [K x NN] row-major: tile rows k0..k0+15, cols n0..n0+127
#pragma unroll
            for (int s = 0; s < 2; s++) {
                int slot = tid + s * 256;
                int row  = slot >> 5;           // 0..15
                int nc   = (slot & 31) * 4;     // 0..124
                *reinterpret_cast<float4*>(&Bs[row][nc]) =
                    *reinterpret_cast<const float4*>(
                        &Bm[(size_t)(k0 + row) * ldb + n0 + nc]);
            }
        }
        __syncthreads();

#pragma unroll
        for (int k = 0; k < BK; k++) {
            float4 a0 = *reinterpret_cast<const float4*>(&As[k][ty * TM]);
            float4 a1 = *reinterpret_cast<const float4*>(&As[k][ty * TM + 4]);
            float4 b0 = *reinterpret_cast<const float4*>(&Bs[k][tx * TN]);
            float4 b1 = *reinterpret_cast<const float4*>(&Bs[k][tx * TN + 4]);
            float ra[TM] = {a0.x, a0.y, a0.z, a0.w, a1.x, a1.y, a1.z, a1.w};
            float rb[TN] = {b0.x, b0.y, b0.z, b0.w, b1.x, b1.y, b1.z, b1.w};
#pragma unroll
            for (int i = 0; i < TM; i++)
#pragma unroll
                for (int j = 0; j < TN; j++)
                    acc[i][j] = fmaf(ra[i], rb[j], acc[i][j]);
        }
        __syncthreads();
    }

#pragma unroll
    for (int i = 0; i < TM; i++) {
        int m = m0 + ty * TM + i;
#pragma unroll
        for (int j = 0; j < TN; j += 4) {
            int n = n0 + tx * TN + j;
            float4 v;
            v.x = alpha * acc[i][j + 0];
            v.y = alpha * acc[i][j + 1];
            v.z = alpha * acc[i][j + 2];
            v.w = alpha * acc[i][j + 3];
            if (bias) {
                v.x += bias[n + 0]; v.y += bias[n + 1];
                v.z += bias[n + 2]; v.w += bias[n + 3];
            }
            *reinterpret_cast<float4*>(&C[(size_t)m * ldc + n]) = v;
        }
    }
}

// ---------------------------------------------------------------------------
// In-place LayerNorm + exact GELU over rows of length D. 1 block / row.
// ---------------------------------------------------------------------------
__global__ void __launch_bounds__(256)
ln_gelu_kernel(float* __restrict__ X, const float* __restrict__ g,
               const float* __restrict__ be)
{
    const int row = blockIdx.x;
    float* x = X + (size_t)row * D;
    const int tid = threadIdx.x;

    float v[4];
    float s = 0.f, s2 = 0.f;
#pragma unroll
    for (int i = 0; i < 4; i++) {
        v[i] = x[tid + i * 256];
        s  += v[i];
        s2 += v[i] * v[i];
    }
#pragma unroll
    for (int o = 16; o; o >>= 1) {
        s  += __shfl_xor_sync(0xffffffffu, s, o);
        s2 += __shfl_xor_sync(0xffffffffu, s2, o);
    }
    __shared__ float shs[8], shs2[8];
    int w = tid >> 5, l = tid & 31;
    if (l == 0) { shs[w] = s; shs2[w] = s2; }
    __syncthreads();
    if (tid == 0) {
        float ts = 0.f, ts2 = 0.f;
#pragma unroll
        for (int i = 0; i < 8; i++) { ts += shs[i]; ts2 += shs2[i]; }
        shs[0] = ts; shs2[0] = ts2;
    }
    __syncthreads();
    const float mu  = shs[0] * (1.f / D);
    const float var = shs2[0] * (1.f / D) - mu * mu;
    const float inv = rsqrtf(var + 1e-5f);
#pragma unroll
    for (int i = 0; i < 4; i++) {
        int c = tid + i * 256;
        float y = (v[i] - mu) * inv * g[c] + be[c];
        x[c] = 0.5f * y * (1.f + erff(y * 0.70710678118654752f));
    }
}

// ---------------------------------------------------------------------------
// Row sum-of-squares. 1 block / row.
// ---------------------------------------------------------------------------
__global__ void __launch_bounds__(256)
rowsq_kernel(const float* __restrict__ X, float* __restrict__ sq)
{
    const int row = blockIdx.x;
    const float* x = X + (size_t)row * D;
    const int tid = threadIdx.x;
    float s = 0.f;
    for (int i = tid; i < D; i += 256) { float v = x[i]; s = fmaf(v, v, s); }
#pragma unroll
    for (int o = 16; o; o >>= 1) s += __shfl_xor_sync(0xffffffffu, s, o);
    __shared__ float sh[8];
    int w = tid >> 5, l = tid & 31;
    if (l == 0) sh[w] = s;
    __syncthreads();
    if (tid == 0) {
        float t = 0.f;
#pragma unroll
        for (int i = 0; i < 8; i++) t += sh[i];
        sq[row] = t;
    }
}

// ---------------------------------------------------------------------------
// Online softmax stats per row of length N: max + 1/sum(exp(x-max)).
// ---------------------------------------------------------------------------
__global__ void __launch_bounds__(256)
softmax_stats_kernel(const float* __restrict__ scores,
                     float* __restrict__ mx, float* __restrict__ rs)
{
    const int bh = blockIdx.x;
    const float* x = scores + (size_t)bh * N;
    const int tid = threadIdx.x;

    float m = -3.0e38f, s = 0.f;
    for (int i = tid; i < N; i += 256) {
        float v = x[i];
        if (v > m) { s = s * expf(m - v) + 1.f; m = v; }
        else        s += expf(v - m);
    }
    __shared__ float sm[256], ss[256];
    sm[tid] = m; ss[tid] = s;
    __syncthreads();
    for (int o = 128; o; o >>= 1) {
        if (tid < o) {
            float m2 = sm[tid + o], s2 = ss[tid + o];
            float mm = fmaxf(sm[tid], m2);
            ss[tid] = ss[tid] * expf(sm[tid] - mm) + s2 * expf(m2 - mm);
            sm[tid] = mm;
        }
        __syncthreads();
    }
    if (tid == 0) { mx[bh] = sm[0]; rs[bh] = 1.f / ss[0]; }
}

// ---------------------------------------------------------------------------
// Fused epilogue for one chunk of BCHUNK query rows:
// cosine/euclid/learned stack -> 3->64->1 MLP -> sigmoid. 1 thread per (b,n).
// dot/out pointers pre-offset by the chunk; qsq pre-offset. scores is the
// chunk buffer indexed [(local_b*H + h)*N + n].
// ---------------------------------------------------------------------------
__global__ void __launch_bounds__(256)
fuse_kernel(const float* __restrict__ dot, const float* __restrict__ scores,
            const float* __restrict__ qsq, const float* __restrict__ ksq,
            const float* __restrict__ mx, const float* __restrict__ rs,
            const float* __restrict__ temp,
            const float* __restrict__ w1, const float* __restrict__ b1,
            const float* __restrict__ w2, const float* __restrict__ b2,
            float* __restrict__ out)
{
    __shared__ float sw1[192], sb1[64], sw2[64];
    const int tid = threadIdx.x;
    if (tid < 192) sw1[tid] = w1[tid];
    if (tid < 64)  { sb1[tid] = b1[tid]; sw2[tid] = w2[tid]; }
    __syncthreads();

    const size_t idx = (size_t)blockIdx.x * 256 + tid;
    const int b = (int)(idx >> 14);        // local b within chunk (/N)
    const int n = (int)(idx & (N - 1));    // %N

    const float dv = dot[idx];
    const float qs = qsq[b];
    const float ks = ksq[n];
    const float expT = expf(*temp);

    const float cosv = dv * rsqrtf(qs * ks) * expT;
    const float d2   = fmaxf(qs + ks - 2.f * dv, 0.f);
    const float euc  = 1.f / (1.f + sqrtf(d2));

    float lsum = 0.f;
    const int bh0 = b * H;
#pragma unroll
    for (int h = 0; h < H; h++) {
        float sc = scores[((size_t)(bh0 + h) << 14) + n];
        lsum += expf(sc - mx[bh0 + h]) * rs[bh0 + h];
    }
    const float learned = lsum * (1.f / H);

    float acc = b2[0];
#pragma unroll 8
    for (int j = 0; j < 64; j++) {
        float hj = fmaf(cosv, sw1[j],
                   fmaf(euc, sw1[64 + j],
                   fmaf(learned, sw1[128 + j], sb1[j])));
        hj = fmaxf(hj, 0.f);
        acc = fmaf(hj, sw2[j], acc);
    }
    out[idx] = 1.f / (1.f + expf(-acc));
}

// ---------------------------------------------------------------------------
// Host launcher
// ---------------------------------------------------------------------------
extern "C" void kernel_launch(void* const* d_in, const int* in_sizes, int n_in,
                              void* d_out, int out_size)
{
    const float* qf   = (const float*)d_in[0];
    const float* cf   = (const float*)d_in[1];
    const float* temp = (const float*)d_in[2];
    const float* q_w1 = (const float*)d_in[3];
    const float* q_b1 = (const float*)d_in[4];
    const float* q_g  = (const float*)d_in[5];
    const float* q_be = (const float*)d_in[6];
    const float* q_w2 = (const float*)d_in[7];
    const float* q_b2 = (const float*)d_in[8];
    const float* k_w1 = (const float*)d_in[9];
    const float* k_b1 = (const float*)d_in[10];
    const float* k_g  = (const float*)d_in[11];
    const float* k_be = (const float*)d_in[12];
    const float* k_w2 = (const float*)d_in[13];
    const float* k_b2 = (const float*)d_in[14];
    const float* wq   = (const float*)d_in[15];
    const float* bq   = (const float*)d_in[16];
    const float* wk   = (const float*)d_in[17];
    const float* bk   = (const float*)d_in[18];
    const float* f_w1 = (const float*)d_in[19];
    const float* f_b1 = (const float*)d_in[20];
    const float* f_w2 = (const float*)d_in[21];
    const float* f_b2 = (const float*)d_in[22];
    float* out = (float*)d_out;

    float *tmp, *kp, *qtmp, *qp, *qh, *dot, *sc, *qsq, *ksq, *mx, *rs;
    cudaGetSymbolAddress((void**)&tmp,  g_tmp);
    cudaGetSymbolAddress((void**)&kp,   g_kp);
    cudaGetSymbolAddress((void**)&qtmp, g_qtmp);
    cudaGetSymbolAddress((void**)&qp,   g_qp);
    cudaGetSymbolAddress((void**)&qh,   g_qh);
    cudaGetSymbolAddress((void**)&dot,  g_dot);
    cudaGetSymbolAddress((void**)&sc,   g_sc);
    cudaGetSymbolAddress((void**)&qsq,  g_qsq);
    cudaGetSymbolAddress((void**)&ksq,  g_ksq);
    cudaGetSymbolAddress((void**)&mx,   g_mx);
    cudaGetSymbolAddress((void**)&rs,   g_rs);

    const float inv_sqrt_hd = 0.088388347648318447f; // 1/sqrt(128)
    float* kh = tmp;  // g_tmp reused for kh after the k-projection consumes it

    // --- K-side projection: kp = proj(cf) ---
    gemm_kernel<false, false><<<dim3(D / BN, N / BM), 256>>>(cf, k_w1, k_b1, tmp,
        N, D, D, D, D, D, 1.f);
    ln_gelu_kernel<<<N, 256>>>(tmp, k_g, k_be);
    gemm_kernel<false, false><<<dim3(D / BN, N / BM), 256>>>(tmp, k_w2, k_b2, kp,
        N, D, D, D, D, D, 1.f);
    // kh = kp @ wk + bk  (overwrites tmp; safe: tmp fully consumed above)
    gemm_kernel<false, false><<<dim3(D / BN, N / BM), 256>>>(kp, wk, bk, kh,
        N, D, D, D, D, D, 1.f);

    // --- Q-side projection: qp = proj(qf) ---
    gemm_kernel<false, false><<<dim3(D / BN, B / BM), 256>>>(qf, q_w1, q_b1, qtmp,
        B, D, D, D, D, D, 1.f);
    ln_gelu_kernel<<<B, 256>>>(qtmp, q_g, q_be);
    gemm_kernel<false, false><<<dim3(D / BN, B / BM), 256>>>(qtmp, q_w2, q_b2, qp,
        B, D, D, D, D, D, 1.f);
    // qh = qp @ wq + bq
    gemm_kernel<false, false><<<dim3(D / BN, B / BM), 256>>>(qp, wq, bq, qh,
        B, D, D, D, D, D, 1.f);

    // --- Row norms ---
    rowsq_kernel<<<B, 256>>>(qp, qsq);
    rowsq_kernel<<<N, 256>>>(kp, ksq);

    // --- dot = qp @ kp^T  [B,N] ---
    gemm_kernel<true, false><<<dim3(N / BN, B / BM), 256>>>(qp, kp, nullptr, dot,
        B, N, D, D, D, N, 1.f);

    // --- scores + softmax + fusion, chunked over query rows ---
    for (int cb = 0; cb < NCHUNKS; cb++) {
        const float* qh_c  = qh  + (size_t)cb * BCHUNK * D;
        const float* dot_c = dot + (size_t)cb * BCHUNK * N;
        const float* qsq_c = qsq + cb * BCHUNK;
        float*       out_c = out + (size_t)cb * BCHUNK * N;

        // sc[(local_b*H + h)*N + n] = dot(qh_c[b, h*HD:], kh[n, h*HD:]) / sqrt(HD)
        gemm_kernel<true, true><<<dim3(N / BN, BCHUNK / BM, H), 256>>>(
            qh_c, kh, nullptr, sc, BCHUNK, N, HD, D, D, H * N, inv_sqrt_hd);

        softmax_stats_kernel<<<BCHUNK * H, 256>>>(sc, mx, rs);

        fuse_kernel<<<((size_t)BCHUNK * N) / 256, 256>>>(dot_c, sc, qsq_c, ksq,
            mx, rs, temp, f_w1, f_b1, f_w2, f_b2, out_c);
    }
}

// round 6
// speedup vs baseline: 1.7012x; 1.7012x over previous
#include <cuda_runtime.h>
#include <cuda_bf16.h>
#include <math.h>
#include <stdint.h>

// Problem constants
constexpr int D  = 1024;   // d_model
constexpr int H  = 8;      // heads
constexpr int HD = 128;    // head dim
constexpr int B  = 1024;   // queries
constexpr int N  = 16384;  // candidates
constexpr int BCHUNK = 128;
constexpr int NCHUNKS = B / BCHUNK;

// ---------------------------------------------------------------------------
// Scratch arena (single static device array, ~305 MB, lifetime-aliased)
// ---------------------------------------------------------------------------
constexpr size_t MB = 1ull << 20;
constexpr size_t OFF_TMP   = 0;          // fp32 [N,D]; later fp32 dot [B,N]
constexpr size_t OFF_CF_H  = 64 * MB;    // bf16 [N,D] cf hi; later kh hi
constexpr size_t OFF_CF_L  = 96 * MB;    // bf16 [N,D] cf lo; later kh lo
constexpr size_t OFF_GK_H  = 128 * MB;   // bf16 [N,D] gelu-k hi; later fp32 sc (spans GK_H..GK_L)
constexpr size_t OFF_GK_L  = 160 * MB;   // bf16 [N,D] gelu-k lo
constexpr size_t OFF_KP_H  = 192 * MB;   // bf16 [N,D] kp hi
constexpr size_t OFF_KP_L  = 224 * MB;   // bf16 [N,D] kp lo
constexpr size_t OFF_QTMP  = 256 * MB;   // fp32 [B,D]
constexpr size_t OFF_QF_H  = 260 * MB;   // bf16 [B,D] pairs, 2MB each
constexpr size_t OFF_QF_L  = 262 * MB;
constexpr size_t OFF_GQ_H  = 264 * MB;
constexpr size_t OFF_GQ_L  = 266 * MB;
constexpr size_t OFF_QP_H  = 268 * MB;
constexpr size_t OFF_QP_L  = 270 * MB;
constexpr size_t OFF_QH_H  = 272 * MB;
constexpr size_t OFF_QH_L  = 274 * MB;
constexpr size_t OFF_W     = 276 * MB;   // 6 weight pairs, each hi(2MB)+lo(2MB) = 24MB
constexpr size_t OFF_QSQ   = 300 * MB;
constexpr size_t OFF_KSQ   = 300 * MB + 8  * 1024;
constexpr size_t OFF_MX    = 300 * MB + 80 * 1024;
constexpr size_t OFF_RS    = 300 * MB + 88 * 1024;
constexpr size_t ARENA_BYTES = 301 * MB;

__device__ __align__(1024) char g_arena[ARENA_BYTES];

// ---------------------------------------------------------------------------
// PTX helpers
// ---------------------------------------------------------------------------
__device__ __forceinline__ void cp16(uint32_t dst, const void* src) {
    asm volatile("cp.async.cg.shared.global [%0], [%1], 16;\n"
                 :: "r"(dst), "l"(src) : "memory");
}
__device__ __forceinline__ void cp_commit() {
    asm volatile("cp.async.commit_group;\n" ::: "memory");
}
__device__ __forceinline__ void ldsm4(uint32_t* r, uint32_t addr) {
    asm volatile("ldmatrix.sync.aligned.m8n8.x4.shared.b16 {%0,%1,%2,%3}, [%4];"
                 : "=r"(r[0]), "=r"(r[1]), "=r"(r[2]), "=r"(r[3]) : "r"(addr));
}
__device__ __forceinline__ void mma16816(float* c, const uint32_t* a,
                                         uint32_t b0, uint32_t b1) {
    asm volatile(
        "mma.sync.aligned.m16n8k16.row.col.f32.bf16.bf16.f32 "
        "{%0,%1,%2,%3},{%4,%5,%6,%7},{%8,%9},{%0,%1,%2,%3};"
        : "+f"(c[0]), "+f"(c[1]), "+f"(c[2]), "+f"(c[3])
        : "r"(a[0]), "r"(a[1]), "r"(a[2]), "r"(a[3]), "r"(b0), "r"(b1));
}
__device__ __forceinline__ void split2(float x, __nv_bfloat16& h, __nv_bfloat16& l) {
    h = __float2bfloat16(x);
    l = __float2bfloat16(x - __bfloat162float(h));
}

// ---------------------------------------------------------------------------
// bf16 split-precision NT GEMM:
//   C[M,NN] = alpha * (A_hi+A_lo)[M,K] @ (B_hi+B_lo)[NN,K]^T (+ bias[NN])
// Tiles 128x128x32, 256 threads (8 warps 2x4), warp tile 64x32,
// mma.m16n8k16 x3 passes (hh, hl, lh). 3-stage cp.async pipeline.
// Smem rows stride 80B -> conflict-free ldmatrix.
// Outputs: Cf (fp32, optional), Ch/Cl (bf16 split pair, optional).
// BATCH_HEADS: blockIdx.z=h offsets A,B by h*HD and Cf by h*N (ldc=H*N).
// ---------------------------------------------------------------------------
constexpr int GBM = 128, GBN = 128, GBK = 32;
constexpr int SSTRIDE_B = 80;                       // bytes per smem row
constexpr int MAT_BYTES = 128 * SSTRIDE_B;          // 10240
constexpr int STAGE_BYTES = 4 * MAT_BYTES;          // Ah, Al, Bh, Bl
constexpr int GEMM_SMEM = 3 * STAGE_BYTES;          // 122880

__device__ __forceinline__ void copy_stage(
    char* sbase,
    const __nv_bfloat16* Ah, const __nv_bfloat16* Al,
    const __nv_bfloat16* Bh, const __nv_bfloat16* Bl,
    int m0, int n0, int k0, int lda, int ldb, int crow, int cj)
{
    const __nv_bfloat16* srcs[4] = {
        Ah + (size_t)(m0 + crow) * lda + k0 + cj * 8,
        Al + (size_t)(m0 + crow) * lda + k0 + cj * 8,
        Bh + (size_t)(n0 + crow) * ldb + k0 + cj * 8,
        Bl + (size_t)(n0 + crow) * ldb + k0 + cj * 8 };
#pragma unroll
    for (int m = 0; m < 4; m++) {
        uint32_t dst = (uint32_t)__cvta_generic_to_shared(
            sbase + m * MAT_BYTES + crow * SSTRIDE_B + cj * 16);
        cp16(dst, srcs[m]);
        cp16(dst + 16, srcs[m] + 8);
    }
}

template <bool BATCH_HEADS>
__global__ void __launch_bounds__(256, 1)
bgemm_kernel(const __nv_bfloat16* __restrict__ Ah, const __nv_bfloat16* __restrict__ Al,
             const __nv_bfloat16* __restrict__ Bh, const __nv_bfloat16* __restrict__ Bl,
             const float* __restrict__ bias, float* __restrict__ Cf,
             __nv_bfloat16* __restrict__ Ch, __nv_bfloat16* __restrict__ Cl,
             int M, int NN, int K, int lda, int ldb, int ldc, float alpha)
{
    extern __shared__ char smem[];
    if (BATCH_HEADS) {
        const int h = blockIdx.z;
        Ah += (size_t)h * HD; Al += (size_t)h * HD;
        Bh += (size_t)h * HD; Bl += (size_t)h * HD;
        Cf += (size_t)h * N;
    }
    const int tid  = threadIdx.x;
    const int m0   = blockIdx.y * GBM;
    const int n0   = blockIdx.x * GBN;
    const int crow = tid >> 1;              // copy row 0..127
    const int cj   = (tid & 1) * 2;         // col-chunk (8 elems each)
    const int lane = tid & 31, warp = tid >> 5;
    const int m_off = (warp & 1) * 64;
    const int n_off = (warp >> 1) * 32;
    const int lrow  = lane & 15;
    const int lcolb = ((lane >> 4) * 8) * 2;  // byte offset of 8-elem col half

    float acc[4][4][4];
#pragma unroll
    for (int i = 0; i < 4; i++)
#pragma unroll
        for (int j = 0; j < 4; j++)
#pragma unroll
            for (int r = 0; r < 4; r++) acc[i][j][r] = 0.f;

    const int T = K / GBK;
    copy_stage(smem, Ah, Al, Bh, Bl, m0, n0, 0, lda, ldb, crow, cj);
    cp_commit();
    if (T > 1) {
        copy_stage(smem + STAGE_BYTES, Ah, Al, Bh, Bl, m0, n0, GBK, lda, ldb, crow, cj);
        cp_commit();
    }

    int s = 0;
    for (int t = 0; t < T; t++) {
        if (t + 2 < T) {
            int s2 = s + 2; if (s2 >= 3) s2 -= 3;
            copy_stage(smem + s2 * STAGE_BYTES, Ah, Al, Bh, Bl,
                       m0, n0, (t + 2) * GBK, lda, ldb, crow, cj);
            cp_commit();
        }
        const int rem = T - 1 - t;
        if (rem >= 2)      asm volatile("cp.async.wait_group 2;\n" ::: "memory");
        else if (rem == 1) asm volatile("cp.async.wait_group 1;\n" ::: "memory");
        else               asm volatile("cp.async.wait_group 0;\n" ::: "memory");
        __syncthreads();

        char* base = smem + s * STAGE_BYTES;
#pragma unroll
        for (int ks = 0; ks < GBK; ks += 16) {
            uint32_t af[2][4][4];   // [hi/lo][m-tile][4 regs]
            uint32_t bf[2][2][4];   // [hi/lo][n16-group][4 regs]
#pragma unroll
            for (int hl = 0; hl < 2; hl++) {
                char* Abase = base + hl * MAT_BYTES;
#pragma unroll
                for (int i = 0; i < 4; i++) {
                    uint32_t addr = (uint32_t)__cvta_generic_to_shared(
                        Abase + (m_off + i * 16 + lrow) * SSTRIDE_B + ks * 2 + lcolb);
                    ldsm4(af[hl][i], addr);
                }
                char* Bbase = base + (2 + hl) * MAT_BYTES;
#pragma unroll
                for (int jj = 0; jj < 2; jj++) {
                    uint32_t addr = (uint32_t)__cvta_generic_to_shared(
                        Bbase + (n_off + jj * 16 + lrow) * SSTRIDE_B + ks * 2 + lcolb);
                    ldsm4(bf[hl][jj], addr);
                }
            }
#pragma unroll
            for (int i = 0; i < 4; i++) {
#pragma unroll
                for (int j = 0; j < 4; j++) {
                    const int jj = j >> 1, jb = j & 1;
                    mma16816(acc[i][j], af[0][i], bf[0][jj][jb], bf[0][jj][jb + 2]); // hh
                    mma16816(acc[i][j], af[0][i], bf[1][jj][jb], bf[1][jj][jb + 2]); // hl
                    mma16816(acc[i][j], af[1][i], bf[0][jj][jb], bf[0][jj][jb + 2]); // lh
                }
            }
        }
        __syncthreads();
        if (++s == 3) s = 0;
    }

    // Epilogue
    const int g = lane >> 2, tig = lane & 3;
#pragma unroll
    for (int i = 0; i < 4; i++) {
        const int mrow = m0 + m_off + i * 16 + g;
#pragma unroll
        for (int j = 0; j < 4; j++) {
            const int nn = n0 + n_off + j * 8 + tig * 2;
            float bv0 = 0.f, bv1 = 0.f;
            if (bias) { bv0 = bias[nn]; bv1 = bias[nn + 1]; }
            const float v0 = fmaf(alpha, acc[i][j][0], bv0);
            const float v1 = fmaf(alpha, acc[i][j][1], bv1);
            const float v2 = fmaf(alpha, acc[i][j][2], bv0);
            const float v3 = fmaf(alpha, acc[i][j][3], bv1);
            const size_t o0 = (size_t)mrow * ldc + nn;
            const size_t o1 = (size_t)(mrow + 8) * ldc + nn;
            if (Cf) {
                *reinterpret_cast<float2*>(Cf + o0) = make_float2(v0, v1);
                *reinterpret_cast<float2*>(Cf + o1) = make_float2(v2, v3);
            }
            if (Ch) {
                __nv_bfloat16 h0, h1, h2, h3, l0, l1, l2, l3;
                split2(v0, h0, l0); split2(v1, h1, l1);
                split2(v2, h2, l2); split2(v3, h3, l3);
                *reinterpret_cast<__nv_bfloat162*>(Ch + o0) = __halves2bfloat162(h0, h1);
                *reinterpret_cast<__nv_bfloat162*>(Ch + o1) = __halves2bfloat162(h2, h3);
                *reinterpret_cast<__nv_bfloat162*>(Cl + o0) = __halves2bfloat162(l0, l1);
                *reinterpret_cast<__nv_bfloat162*>(Cl + o1) = __halves2bfloat162(l2, l3);
            }
        }
    }
}

// ---------------------------------------------------------------------------
// fp32 -> bf16 hi/lo elementwise split (vectorized by 4)
// ---------------------------------------------------------------------------
__global__ void __launch_bounds__(256)
split_kernel(const float4* __restrict__ X, __nv_bfloat162* __restrict__ Hh,
             __nv_bfloat162* __restrict__ Ll, int n4)
{
    const int idx = blockIdx.x * 256 + threadIdx.x;
    if (idx >= n4) return;
    const float4 v = X[idx];
    __nv_bfloat16 h0, h1, h2, h3, l0, l1, l2, l3;
    split2(v.x, h0, l0); split2(v.y, h1, l1);
    split2(v.z, h2, l2); split2(v.w, h3, l3);
    Hh[idx * 2 + 0] = __halves2bfloat162(h0, h1);
    Hh[idx * 2 + 1] = __halves2bfloat162(h2, h3);
    Ll[idx * 2 + 0] = __halves2bfloat162(l0, l1);
    Ll[idx * 2 + 1] = __halves2bfloat162(l2, l3);
}

// ---------------------------------------------------------------------------
// Weight [K=D, N=D] fp32 -> transposed bf16 hi/lo [N=D, K=D]
// ---------------------------------------------------------------------------
__global__ void __launch_bounds__(256)
transpose_split_kernel(const float* __restrict__ W,
                       __nv_bfloat16* __restrict__ Th, __nv_bfloat16* __restrict__ Tl)
{
    __shared__ float tile[32][33];
    const int n0 = blockIdx.x * 32, k0 = blockIdx.y * 32;
#pragma unroll
    for (int r = 0; r < 32; r += 8)
        tile[threadIdx.y + r][threadIdx.x] =
            W[(size_t)(k0 + threadIdx.y + r) * D + n0 + threadIdx.x];
    __syncthreads();
#pragma unroll
    for (int r = 0; r < 32; r += 8) {
        const float v = tile[threadIdx.x][threadIdx.y + r];
        __nv_bfloat16 h, l;
        split2(v, h, l);
        const size_t o = (size_t)(n0 + threadIdx.y + r) * D + k0 + threadIdx.x;
        Th[o] = h; Tl[o] = l;
    }
}

// ---------------------------------------------------------------------------
// LayerNorm + exact GELU over rows of length D; writes bf16 hi/lo pair.
// ---------------------------------------------------------------------------
__global__ void __launch_bounds__(256)
ln_gelu_split_kernel(const float* __restrict__ X, const float* __restrict__ g,
                     const float* __restrict__ be,
                     __nv_bfloat16* __restrict__ Oh, __nv_bfloat16* __restrict__ Ol)
{
    const int row = blockIdx.x;
    const float* x = X + (size_t)row * D;
    const int tid = threadIdx.x;

    float v[4];
    float s = 0.f, s2 = 0.f;
#pragma unroll
    for (int i = 0; i < 4; i++) {
        v[i] = x[tid + i * 256];
        s  += v[i];
        s2 += v[i] * v[i];
    }
#pragma unroll
    for (int o = 16; o; o >>= 1) {
        s  += __shfl_xor_sync(0xffffffffu, s, o);
        s2 += __shfl_xor_sync(0xffffffffu, s2, o);
    }
    __shared__ float shs[8], shs2[8];
    const int w = tid >> 5, l = tid & 31;
    if (l == 0) { shs[w] = s; shs2[w] = s2; }
    __syncthreads();
    if (tid == 0) {
        float ts = 0.f, ts2 = 0.f;
#pragma unroll
        for (int i = 0; i < 8; i++) { ts += shs[i]; ts2 += shs2[i]; }
        shs[0] = ts; shs2[0] = ts2;
    }
    __syncthreads();
    const float mu  = shs[0] * (1.f / D);
    const float var = shs2[0] * (1.f / D) - mu * mu;
    const float inv = rsqrtf(var + 1e-5f);
#pragma unroll
    for (int i = 0; i < 4; i++) {
        const int c = tid + i * 256;
        const float yy = (v[i] - mu) * inv * g[c] + be[c];
        const float ge = 0.5f * yy * (1.f + erff(yy * 0.70710678118654752f));
        __nv_bfloat16 h, lo;
        split2(ge, h, lo);
        Oh[(size_t)row * D + c] = h;
        Ol[(size_t)row * D + c] = lo;
    }
}

// ---------------------------------------------------------------------------
// Row sum-of-squares from a bf16 hi/lo split pair. 1 block / row.
// ---------------------------------------------------------------------------
__global__ void __launch_bounds__(256)
rowsq_split_kernel(const __nv_bfloat16* __restrict__ Xh,
                   const __nv_bfloat16* __restrict__ Xl, float* __restrict__ sq)
{
    const int row = blockIdx.x;
    const __nv_bfloat16* xh = Xh + (size_t)row * D;
    const __nv_bfloat16* xl = Xl + (size_t)row * D;
    const int tid = threadIdx.x;
    float s = 0.f;
    for (int i = tid; i < D; i += 256) {
        const float v = __bfloat162float(xh[i]) + __bfloat162float(xl[i]);
        s = fmaf(v, v, s);
    }
#pragma unroll
    for (int o = 16; o; o >>= 1) s += __shfl_xor_sync(0xffffffffu, s, o);
    __shared__ float sh[8];
    const int w = tid >> 5, l = tid & 31;
    if (l == 0) sh[w] = s;
    __syncthreads();
    if (tid == 0) {
        float t = 0.f;
#pragma unroll
        for (int i = 0; i < 8; i++) t += sh[i];
        sq[row] = t;
    }
}

// ---------------------------------------------------------------------------
// Online softmax stats per row of length N: max + 1/sum(exp(x-max)).
// ---------------------------------------------------------------------------
__global__ void __launch_bounds__(256)
softmax_stats_kernel(const float* __restrict__ scores,
                     float* __restrict__ mx, float* __restrict__ rs)
{
    const int bh = blockIdx.x;
    const float* x = scores + (size_t)bh * N;
    const int tid = threadIdx.x;

    float m = -3.0e38f, s = 0.f;
    for (int i = tid; i < N; i += 256) {
        float v = x[i];
        if (v > m) { s = s * expf(m - v) + 1.f; m = v; }
        else        s += expf(v - m);
    }
    __shared__ float sm[256], ss[256];
    sm[tid] = m; ss[tid] = s;
    __syncthreads();
    for (int o = 128; o; o >>= 1) {
        if (tid < o) {
            float m2 = sm[tid + o], s2 = ss[tid + o];
            float mm = fmaxf(sm[tid], m2);
            ss[tid] = ss[tid] * expf(sm[tid] - mm) + s2 * expf(m2 - mm);
            sm[tid] = mm;
        }
        __syncthreads();
    }
    if (tid == 0) { mx[bh] = sm[0]; rs[bh] = 1.f / ss[0]; }
}

// ---------------------------------------------------------------------------
// Fused epilogue for one chunk of BCHUNK query rows.
// ---------------------------------------------------------------------------
__global__ void __launch_bounds__(256)
fuse_kernel(const float* __restrict__ dot, const float* __restrict__ scores,
            const float* __restrict__ qsq, const float* __restrict__ ksq,
            const float* __restrict__ mx, const float* __restrict__ rs,
            const float* __restrict__ temp,
            const float* __restrict__ w1, const float* __restrict__ b1,
            const float* __restrict__ w2, const float* __restrict__ b2,
            float* __restrict__ out)
{
    __shared__ float sw1[192], sb1[64], sw2[64];
    const int tid = threadIdx.x;
    if (tid < 192) sw1[tid] = w1[tid];
    if (tid < 64)  { sb1[tid] = b1[tid]; sw2[tid] = w2[tid]; }
    __syncthreads();

    const size_t idx = (size_t)blockIdx.x * 256 + tid;
    const int b = (int)(idx >> 14);        // local b within chunk
    const int n = (int)(idx & (N - 1));

    const float dv = dot[idx];
    const float qs = qsq[b];
    const float ks = ksq[n];
    const float expT = expf(*temp);

    const float cosv = dv * rsqrtf(qs * ks) * expT;
    const float d2   = fmaxf(qs + ks - 2.f * dv, 0.f);
    const float euc  = 1.f / (1.f + sqrtf(d2));

    float lsum = 0.f;
    const int bh0 = b * H;
#pragma unroll
    for (int h = 0; h < H; h++) {
        float sc = scores[((size_t)(bh0 + h) << 14) + n];
        lsum += expf(sc - mx[bh0 + h]) * rs[bh0 + h];
    }
    const float learned = lsum * (1.f / H);

    float acc = b2[0];
#pragma unroll 8
    for (int j = 0; j < 64; j++) {
        float hj = fmaf(cosv, sw1[j],
                   fmaf(euc, sw1[64 + j],
                   fmaf(learned, sw1[128 + j], sb1[j])));
        hj = fmaxf(hj, 0.f);
        acc = fmaf(hj, sw2[j], acc);
    }
    out[idx] = 1.f / (1.f + expf(-acc));
}

// ---------------------------------------------------------------------------
// Host launcher
// ---------------------------------------------------------------------------
extern "C" void kernel_launch(void* const* d_in, const int* in_sizes, int n_in,
                              void* d_out, int out_size)
{
    const float* qf   = (const float*)d_in[0];
    const float* cf   = (const float*)d_in[1];
    const float* temp = (const float*)d_in[2];
    const float* q_w1 = (const float*)d_in[3];
    const float* q_b1 = (const float*)d_in[4];
    const float* q_g  = (const float*)d_in[5];
    const float* q_be = (const float*)d_in[6];
    const float* q_w2 = (const float*)d_in[7];
    const float* q_b2 = (const float*)d_in[8];
    const float* k_w1 = (const float*)d_in[9];
    const float* k_b1 = (const float*)d_in[10];
    const float* k_g  = (const float*)d_in[11];
    const float* k_be = (const float*)d_in[12];
    const float* k_w2 = (const float*)d_in[13];
    const float* k_b2 = (const float*)d_in[14];
    const float* wq   = (const float*)d_in[15];
    const float* bq   = (const float*)d_in[16];
    const float* wk   = (const float*)d_in[17];
    const float* bk   = (const float*)d_in[18];
    const float* f_w1 = (const float*)d_in[19];
    const float* f_b1 = (const float*)d_in[20];
    const float* f_w2 = (const float*)d_in[21];
    const float* f_b2 = (const float*)d_in[22];
    float* out = (float*)d_out;

    char* base;
    cudaGetSymbolAddress((void**)&base, g_arena);
    typedef __nv_bfloat16 bf;

    float* tmp  = (float*)(base + OFF_TMP);
    float* dot  = (float*)(base + OFF_TMP);      // alias (tmp dead by then)
    bf*  cf_h   = (bf*)(base + OFF_CF_H);
    bf*  cf_l   = (bf*)(base + OFF_CF_L);
    bf*  kh_h   = (bf*)(base + OFF_CF_H);        // alias (cf dead after GEMM1)
    bf*  kh_l   = (bf*)(base + OFF_CF_L);
    bf*  gk_h   = (bf*)(base + OFF_GK_H);
    bf*  gk_l   = (bf*)(base + OFF_GK_L);
    float* sc   = (float*)(base + OFF_GK_H);     // alias, spans GK_H..GK_L (64MB)
    bf*  kp_h   = (bf*)(base + OFF_KP_H);
    bf*  kp_l   = (bf*)(base + OFF_KP_L);
    float* qtmp = (float*)(base + OFF_QTMP);
    bf*  qf_h   = (bf*)(base + OFF_QF_H);
    bf*  qf_l   = (bf*)(base + OFF_QF_L);
    bf*  gq_h   = (bf*)(base + OFF_GQ_H);
    bf*  gq_l   = (bf*)(base + OFF_GQ_L);
    bf*  qp_h   = (bf*)(base + OFF_QP_H);
    bf*  qp_l   = (bf*)(base + OFF_QP_L);
    bf*  qh_h   = (bf*)(base + OFF_QH_H);
    bf*  qh_l   = (bf*)(base + OFF_QH_L);
    float* qsq  = (float*)(base + OFF_QSQ);
    float* ksq  = (float*)(base + OFF_KSQ);
    float* mx   = (float*)(base + OFF_MX);
    float* rs   = (float*)(base + OFF_RS);

    // 6 transposed+split weights: 0:k_w1 1:k_w2 2:wk 3:q_w1 4:q_w2 5:wq
    bf* wth[6]; bf* wtl[6];
    const float* wsrc[6] = {k_w1, k_w2, wk, q_w1, q_w2, wq};
    for (int i = 0; i < 6; i++) {
        wth[i] = (bf*)(base + OFF_W + (size_t)i * 4 * MB);
        wtl[i] = (bf*)(base + OFF_W + (size_t)i * 4 * MB + 2 * MB);
    }

    cudaFuncSetAttribute(bgemm_kernel<false>,
        cudaFuncAttributeMaxDynamicSharedMemorySize, GEMM_SMEM);
    cudaFuncSetAttribute(bgemm_kernel<true>,
        cudaFuncAttributeMaxDynamicSharedMemorySize, GEMM_SMEM);

    const float inv_sqrt_hd = 0.088388347648318447f; // 1/sqrt(128)

    // --- Prep: weight transpose+split, input splits ---
    for (int i = 0; i < 6; i++)
        transpose_split_kernel<<<dim3(32, 32), dim3(32, 8)>>>(wsrc[i], wth[i], wtl[i]);
    split_kernel<<<(N * D / 4 + 255) / 256, 256>>>(
        (const float4*)cf, (__nv_bfloat162*)cf_h, (__nv_bfloat162*)cf_l, N * D / 4);
    split_kernel<<<(B * D / 4 + 255) / 256, 256>>>(
        (const float4*)qf, (__nv_bfloat162*)qf_h, (__nv_bfloat162*)qf_l, B * D / 4);

    // --- K-side projection ---
    bgemm_kernel<false><<<dim3(D / GBN, N / GBM), 256, GEMM_SMEM>>>(
        cf_h, cf_l, wth[0], wtl[0], k_b1, tmp, nullptr, nullptr,
        N, D, D, D, D, D, 1.f);
    ln_gelu_split_kernel<<<N, 256>>>(tmp, k_g, k_be, gk_h, gk_l);
    bgemm_kernel<false><<<dim3(D / GBN, N / GBM), 256, GEMM_SMEM>>>(
        gk_h, gk_l, wth[1], wtl[1], k_b2, nullptr, kp_h, kp_l,
        N, D, D, D, D, D, 1.f);
    bgemm_kernel<false><<<dim3(D / GBN, N / GBM), 256, GEMM_SMEM>>>(
        kp_h, kp_l, wth[2], wtl[2], bk, nullptr, kh_h, kh_l,
        N, D, D, D, D, D, 1.f);

    // --- Q-side projection ---
    bgemm_kernel<false><<<dim3(D / GBN, B / GBM), 256, GEMM_SMEM>>>(
        qf_h, qf_l, wth[3], wtl[3], q_b1, qtmp, nullptr, nullptr,
        B, D, D, D, D, D, 1.f);
    ln_gelu_split_kernel<<<B, 256>>>(qtmp, q_g, q_be, gq_h, gq_l);
    bgemm_kernel<false><<<dim3(D / GBN, B / GBM), 256, GEMM_SMEM>>>(
        gq_h, gq_l, wth[4], wtl[4], q_b2, nullptr, qp_h, qp_l,
        B, D, D, D, D, D, 1.f);
    bgemm_kernel<false><<<dim3(D / GBN, B / GBM), 256, GEMM_SMEM>>>(
        qp_h, qp_l, wth[5], wtl[5], bq, nullptr, qh_h, qh_l,
        B, D, D, D, D, D, 1.f);

    // --- Row norms (from split pairs) ---
    rowsq_split_kernel<<<B, 256>>>(qp_h, qp_l, qsq);
    rowsq_split_kernel<<<N, 256>>>(kp_h, kp_l, ksq);

    // --- dot = qp @ kp^T [B,N] (overwrites tmp region) ---
    bgemm_kernel<false><<<dim3(N / GBN, B / GBM), 256, GEMM_SMEM>>>(
        qp_h, qp_l, kp_h, kp_l, nullptr, dot, nullptr, nullptr,
        B, N, D, D, D, N, 1.f);

    // --- scores + softmax + fusion, chunked over query rows ---
    for (int cb = 0; cb < NCHUNKS; cb++) {
        const bf* qhh_c = qh_h + (size_t)cb * BCHUNK * D;
        const bf* qhl_c = qh_l + (size_t)cb * BCHUNK * D;
        const float* dot_c = dot + (size_t)cb * BCHUNK * N;
        const float* qsq_c = qsq + cb * BCHUNK;
        float* out_c = out + (size_t)cb * BCHUNK * N;

        bgemm_kernel<true><<<dim3(N / GBN, BCHUNK / GBM, H), 256, GEMM_SMEM>>>(
            qhh_c, qhl_c, kh_h, kh_l, nullptr, sc, nullptr, nullptr,
            BCHUNK, N, HD, D, D, H * N, inv_sqrt_hd);

        softmax_stats_kernel<<<BCHUNK * H, 256>>>(sc, mx, rs);

        fuse_kernel<<<((size_t)BCHUNK * N) / 256, 256>>>(dot_c, sc, qsq_c, ksq,
            mx, rs, temp, f_w1, f_b1, f_w2, f_b2, out_c);
    }
}

// round 9
// speedup vs baseline: 2.1512x; 1.2645x over previous
#include <cuda_runtime.h>
#include <cuda_fp16.h>
#include <math.h>
#include <stdint.h>

// Problem constants
constexpr int D  = 1024;   // d_model
constexpr int H  = 8;      // heads
constexpr int HD = 128;    // head dim
constexpr int B  = 1024;   // queries
constexpr int N  = 16384;  // candidates
constexpr int BCHUNK = 128;
constexpr int NCHUNKS = B / BCHUNK;

// ---------------------------------------------------------------------------
// Scratch arena (single static device array, ~301 MB, lifetime-aliased)
// ---------------------------------------------------------------------------
constexpr size_t MB = 1ull << 20;
constexpr size_t OFF_TMP   = 0;          // fp32 [N,D]; later fp32 dot [B,N]
constexpr size_t OFF_CF_H  = 64 * MB;    // fp16 [N,D] cf hi; later kh hi
constexpr size_t OFF_CF_L  = 96 * MB;    // fp16 [N,D] cf lo
constexpr size_t OFF_GK_H  = 128 * MB;   // fp16 [N,D] gelu-k hi; later fp32 sc
constexpr size_t OFF_GK_L  = 160 * MB;   // fp16 [N,D] gelu-k lo
constexpr size_t OFF_KP_H  = 192 * MB;   // fp16 [N,D] kp hi (B-role: hi only)
constexpr size_t OFF_KP_L  = 224 * MB;   // (spare)
constexpr size_t OFF_QTMP  = 256 * MB;   // fp32 [B,D]
constexpr size_t OFF_QF_H  = 260 * MB;   // fp16 [B,D] pairs, 2MB each
constexpr size_t OFF_QF_L  = 262 * MB;
constexpr size_t OFF_GQ_H  = 264 * MB;
constexpr size_t OFF_GQ_L  = 266 * MB;
constexpr size_t OFF_QP_H  = 268 * MB;
constexpr size_t OFF_QP_L  = 270 * MB;
constexpr size_t OFF_QH_H  = 272 * MB;
constexpr size_t OFF_QH_L  = 274 * MB;
constexpr size_t OFF_W     = 276 * MB;   // 6 transposed fp16 weights (hi), 2MB each
constexpr size_t OFF_QSQ   = 300 * MB;
constexpr size_t OFF_KSQ   = 300 * MB + 8  * 1024;
constexpr size_t OFF_MX    = 300 * MB + 80 * 1024;
constexpr size_t OFF_RS    = 300 * MB + 88 * 1024;
constexpr size_t ARENA_BYTES = 301 * MB;

__device__ __align__(1024) char g_arena[ARENA_BYTES];

// ---------------------------------------------------------------------------
// PTX helpers
// ---------------------------------------------------------------------------
__device__ __forceinline__ void cp16(uint32_t dst, const void* src) {
    asm volatile("cp.async.cg.shared.global [%0], [%1], 16;\n"
                 :: "r"(dst), "l"(src) : "memory");
}
__device__ __forceinline__ void cp_commit() {
    asm volatile("cp.async.commit_group;\n" ::: "memory");
}
__device__ __forceinline__ void ldsm4(uint32_t* r, uint32_t addr) {
    asm volatile("ldmatrix.sync.aligned.m8n8.x4.shared.b16 {%0,%1,%2,%3}, [%4];"
                 : "=r"(r[0]), "=r"(r[1]), "=r"(r[2]), "=r"(r[3]) : "r"(addr));
}
__device__ __forceinline__ void mma16816(float* c, const uint32_t* a,
                                         uint32_t b0, uint32_t b1) {
    asm volatile(
        "mma.sync.aligned.m16n8k16.row.col.f32.f16.f16.f32 "
        "{%0,%1,%2,%3},{%4,%5,%6,%7},{%8,%9},{%0,%1,%2,%3};"
        : "+f"(c[0]), "+f"(c[1]), "+f"(c[2]), "+f"(c[3])
        : "r"(a[0]), "r"(a[1]), "r"(a[2]), "r"(a[3]), "r"(b0), "r"(b1));
}
__device__ __forceinline__ void split2h(float x, __half& h, __half& l) {
    h = __float2half_rn(x);
    l = __float2half_rn(x - __half2float(h));
}

// ---------------------------------------------------------------------------
// fp16 2-pass split NT GEMM:
//   C[M,NN] = alpha * (A_hi+A_lo)[M,K] @ B_h[NN,K]^T (+ bias[NN])
// Tiles 128x128x32, 256 threads (8 warps 2x4), warp tile 64x32,
// mma.m16n8k16 x2 passes (Ah*Bh, Al*Bh). 4-stage cp.async pipeline.
// Smem rows stride 80B -> conflict-free ldmatrix.
// Outputs: Cf (fp32, opt), Ch (fp16 hi, opt), Cl (fp16 lo, opt — may be null
// while Ch set, for B-role-only outputs).
// BATCH_HEADS: blockIdx.z=h offsets A,B by h*HD and Cf by h*N (ldc=H*N).
// ---------------------------------------------------------------------------
constexpr int GBM = 128, GBN = 128, GBK = 32;
constexpr int SSTRIDE_B = 80;                       // bytes per smem row
constexpr int MAT_BYTES = 128 * SSTRIDE_B;          // 10240
constexpr int STAGE_BYTES = 3 * MAT_BYTES;          // Ah, Al, Bh
constexpr int NSTAGE = 4;
constexpr int GEMM_SMEM = NSTAGE * STAGE_BYTES;     // 122880

__device__ __forceinline__ void copy_stage(
    char* sbase,
    const __half* Ah, const __half* Al, const __half* Bh,
    int m0, int n0, int k0, int lda, int ldb, int crow, int cj)
{
    const __half* srcs[3] = {
        Ah + (size_t)(m0 + crow) * lda + k0 + cj * 8,
        Al + (size_t)(m0 + crow) * lda + k0 + cj * 8,
        Bh + (size_t)(n0 + crow) * ldb + k0 + cj * 8 };
#pragma unroll
    for (int m = 0; m < 3; m++) {
        uint32_t dst = (uint32_t)__cvta_generic_to_shared(
            sbase + m * MAT_BYTES + crow * SSTRIDE_B + cj * 16);
        cp16(dst, srcs[m]);
        cp16(dst + 16, srcs[m] + 8);
    }
}

template <bool BATCH_HEADS>
__global__ void __launch_bounds__(256, 1)
bgemm_kernel(const __half* __restrict__ Ah, const __half* __restrict__ Al,
             const __half* __restrict__ Bh,
             const float* __restrict__ bias, float* __restrict__ Cf,
             __half* __restrict__ Ch, __half* __restrict__ Cl,
             int M, int NN, int K, int lda, int ldb, int ldc, float alpha)
{
    extern __shared__ char smem[];
    if (BATCH_HEADS) {
        const int h = blockIdx.z;
        Ah += (size_t)h * HD; Al += (size_t)h * HD;
        Bh += (size_t)h * HD;
        Cf += (size_t)h * N;
    }
    const int tid  = threadIdx.x;
    const int m0   = blockIdx.y * GBM;
    const int n0   = blockIdx.x * GBN;
    const int crow = tid >> 1;              // copy row 0..127
    const int cj   = (tid & 1) * 2;         // col-chunk (8 elems each)
    const int lane = tid & 31, warp = tid >> 5;
    const int m_off = (warp & 1) * 64;
    const int n_off = (warp >> 1) * 32;
    const int lrow  = lane & 15;
    const int lcolb = ((lane >> 4) * 8) * 2;  // byte offset of 8-elem col half

    float acc[4][4][4];
#pragma unroll
    for (int i = 0; i < 4; i++)
#pragma unroll
        for (int j = 0; j < 4; j++)
#pragma unroll
            for (int r = 0; r < 4; r++) acc[i][j][r] = 0.f;

    const int T = K / GBK;
    const int nf = (T < 3) ? T : 3;
    for (int f = 0; f < nf; f++) {
        copy_stage(smem + f * STAGE_BYTES, Ah, Al, Bh, m0, n0, f * GBK,
                   lda, ldb, crow, cj);
        cp_commit();
    }

    for (int t = 0; t < T; t++) {
        if (t + 3 < T) {
            copy_stage(smem + ((t + 3) & 3) * STAGE_BYTES, Ah, Al, Bh,
                       m0, n0, (t + 3) * GBK, lda, ldb, crow, cj);
            cp_commit();
        }
        const int rem = T - 1 - t;
        if (rem >= 3)      asm volatile("cp.async.wait_group 3;\n" ::: "memory");
        else if (rem == 2) asm volatile("cp.async.wait_group 2;\n" ::: "memory");
        else if (rem == 1) asm volatile("cp.async.wait_group 1;\n" ::: "memory");
        else               asm volatile("cp.async.wait_group 0;\n" ::: "memory");
        __syncthreads();

        char* base = smem + (t & 3) * STAGE_BYTES;
#pragma unroll
        for (int ks = 0; ks < GBK; ks += 16) {
            uint32_t af[2][4][4];   // [hi/lo][m-tile][4 regs]
            uint32_t bfr[2][4];     // [n16-group][4 regs]
#pragma unroll
            for (int hl = 0; hl < 2; hl++) {
                char* Abase = base + hl * MAT_BYTES;
#pragma unroll
                for (int i = 0; i < 4; i++) {
                    uint32_t addr = (uint32_t)__cvta_generic_to_shared(
                        Abase + (m_off + i * 16 + lrow) * SSTRIDE_B + ks * 2 + lcolb);
                    ldsm4(af[hl][i], addr);
                }
            }
            {
                char* Bbase = base + 2 * MAT_BYTES;
#pragma unroll
                for (int jj = 0; jj < 2; jj++) {
                    uint32_t addr = (uint32_t)__cvta_generic_to_shared(
                        Bbase + (n_off + jj * 16 + lrow) * SSTRIDE_B + ks * 2 + lcolb);
                    ldsm4(bfr[jj], addr);
                }
            }
#pragma unroll
            for (int i = 0; i < 4; i++) {
#pragma unroll
                for (int j = 0; j < 4; j++) {
                    const int jj = j >> 1, jb = j & 1;
                    mma16816(acc[i][j], af[0][i], bfr[jj][jb], bfr[jj][jb + 2]); // Ah*Bh
                    mma16816(acc[i][j], af[1][i], bfr[jj][jb], bfr[jj][jb + 2]); // Al*Bh
                }
            }
        }
        __syncthreads();
    }

    // Epilogue
    const int g = lane >> 2, tig = lane & 3;
#pragma unroll
    for (int i = 0; i < 4; i++) {
        const int mrow = m0 + m_off + i * 16 + g;
#pragma unroll
        for (int j = 0; j < 4; j++) {
            const int nn = n0 + n_off + j * 8 + tig * 2;
            float bv0 = 0.f, bv1 = 0.f;
            if (bias) { bv0 = bias[nn]; bv1 = bias[nn + 1]; }
            const float v0 = fmaf(alpha, acc[i][j][0], bv0);
            const float v1 = fmaf(alpha, acc[i][j][1], bv1);
            const float v2 = fmaf(alpha, acc[i][j][2], bv0);
            const float v3 = fmaf(alpha, acc[i][j][3], bv1);
            const size_t o0 = (size_t)mrow * ldc + nn;
            const size_t o1 = (size_t)(mrow + 8) * ldc + nn;
            if (Cf) {
                *reinterpret_cast<float2*>(Cf + o0) = make_float2(v0, v1);
                *reinterpret_cast<float2*>(Cf + o1) = make_float2(v2, v3);
            }
            if (Ch) {
                if (Cl) {
                    __half h0, h1, h2, h3, l0, l1, l2, l3;
                    split2h(v0, h0, l0); split2h(v1, h1, l1);
                    split2h(v2, h2, l2); split2h(v3, h3, l3);
                    *reinterpret_cast<__half2*>(Ch + o0) = __halves2half2(h0, h1);
                    *reinterpret_cast<__half2*>(Ch + o1) = __halves2half2(h2, h3);
                    *reinterpret_cast<__half2*>(Cl + o0) = __halves2half2(l0, l1);
                    *reinterpret_cast<__half2*>(Cl + o1) = __halves2half2(l2, l3);
                } else {
                    *reinterpret_cast<__half2*>(Ch + o0) =
                        __halves2half2(__float2half_rn(v0), __float2half_rn(v1));
                    *reinterpret_cast<__half2*>(Ch + o1) =
                        __halves2half2(__float2half_rn(v2), __float2half_rn(v3));
                }
            }
        }
    }
}

// ---------------------------------------------------------------------------
// fp32 -> fp16 hi/lo elementwise split (vectorized by 4)
// ---------------------------------------------------------------------------
__global__ void __launch_bounds__(256)
split_kernel(const float4* __restrict__ X, __half2* __restrict__ Hh,
             __half2* __restrict__ Ll, int n4)
{
    const int idx = blockIdx.x * 256 + threadIdx.x;
    if (idx >= n4) return;
    const float4 v = X[idx];
    __half h0, h1, h2, h3, l0, l1, l2, l3;
    split2h(v.x, h0, l0); split2h(v.y, h1, l1);
    split2h(v.z, h2, l2); split2h(v.w, h3, l3);
    Hh[idx * 2 + 0] = __halves2half2(h0, h1);
    Hh[idx * 2 + 1] = __halves2half2(h2, h3);
    Ll[idx * 2 + 0] = __halves2half2(l0, l1);
    Ll[idx * 2 + 1] = __halves2half2(l2, l3);
}

// ---------------------------------------------------------------------------
// Weight [K=D, N=D] fp32 -> transposed fp16 (hi only) [N=D, K=D]
// ---------------------------------------------------------------------------
__global__ void __launch_bounds__(256)
transpose_h_kernel(const float* __restrict__ W, __half* __restrict__ Th)
{
    __shared__ float tile[32][33];
    const int n0 = blockIdx.x * 32, k0 = blockIdx.y * 32;
#pragma unroll
    for (int r = 0; r < 32; r += 8)
        tile[threadIdx.y + r][threadIdx.x] =
            W[(size_t)(k0 + threadIdx.y + r) * D + n0 + threadIdx.x];
    __syncthreads();
#pragma unroll
    for (int r = 0; r < 32; r += 8) {
        const float v = tile[threadIdx.x][threadIdx.y + r];
        Th[(size_t)(n0 + threadIdx.y + r) * D + k0 + threadIdx.x] =
            __float2half_rn(v);
    }
}

// ---------------------------------------------------------------------------
// LayerNorm + exact GELU over rows of length D; writes fp16 hi/lo pair.
// ---------------------------------------------------------------------------
__global__ void __launch_bounds__(256)
ln_gelu_split_kernel(const float* __restrict__ X, const float* __restrict__ g,
                     const float* __restrict__ be,
                     __half* __restrict__ Oh, __half* __restrict__ Ol)
{
    const int row = blockIdx.x;
    const float* x = X + (size_t)row * D;
    const int tid = threadIdx.x;

    float v[4];
    float s = 0.f, s2 = 0.f;
#pragma unroll
    for (int i = 0; i < 4; i++) {
        v[i] = x[tid + i * 256];
        s  += v[i];
        s2 += v[i] * v[i];
    }
#pragma unroll
    for (int o = 16; o; o >>= 1) {
        s  += __shfl_xor_sync(0xffffffffu, s, o);
        s2 += __shfl_xor_sync(0xffffffffu, s2, o);
    }
    __shared__ float shs[8], shs2[8];
    const int w = tid >> 5, l = tid & 31;
    if (l == 0) { shs[w] = s; shs2[w] = s2; }
    __syncthreads();
    if (tid == 0) {
        float ts = 0.f, ts2 = 0.f;
#pragma unroll
        for (int i = 0; i < 8; i++) { ts += shs[i]; ts2 += shs2[i]; }
        shs[0] = ts; shs2[0] = ts2;
    }
    __syncthreads();
    const float mu  = shs[0] * (1.f / D);
    const float var = shs2[0] * (1.f / D) - mu * mu;
    const float inv = rsqrtf(var + 1e-5f);
#pragma unroll
    for (int i = 0; i < 4; i++) {
        const int c = tid + i * 256;
        const float yy = (v[i] - mu) * inv * g[c] + be[c];
        const float ge = 0.5f * yy * (1.f + erff(yy * 0.70710678118654752f));
        __half h, lo;
        split2h(ge, h, lo);
        Oh[(size_t)row * D + c] = h;
        Ol[(size_t)row * D + c] = lo;
    }
}

// ---------------------------------------------------------------------------
// Row sum-of-squares. HL variant: hi+lo pair; H variant: hi only.
// ---------------------------------------------------------------------------
__global__ void __launch_bounds__(256)
rowsq_hl_kernel(const __half* __restrict__ Xh, const __half* __restrict__ Xl,
                float* __restrict__ sq)
{
    const int row = blockIdx.x;
    const __half* xh = Xh + (size_t)row * D;
    const __half* xl = Xl + (size_t)row * D;
    const int tid = threadIdx.x;
    float s = 0.f;
    for (int i = tid; i < D; i += 256) {
        const float v = __half2float(xh[i]) + __half2float(xl[i]);
        s = fmaf(v, v, s);
    }
#pragma unroll
    for (int o = 16; o; o >>= 1) s += __shfl_xor_sync(0xffffffffu, s, o);
    __shared__ float sh[8];
    const int w = tid >> 5, l = tid & 31;
    if (l == 0) sh[w] = s;
    __syncthreads();
    if (tid == 0) {
        float t = 0.f;
#pragma unroll
        for (int i = 0; i < 8; i++) t += sh[i];
        sq[row] = t;
    }
}

__global__ void __launch_bounds__(256)
rowsq_h_kernel(const __half* __restrict__ Xh, float* __restrict__ sq)
{
    const int row = blockIdx.x;
    const __half* xh = Xh + (size_t)row * D;
    const int tid = threadIdx.x;
    float s = 0.f;
    for (int i = tid; i < D; i += 256) {
        const float v = __half2float(xh[i]);
        s = fmaf(v, v, s);
    }
#pragma unroll
    for (int o = 16; o; o >>= 1) s += __shfl_xor_sync(0xffffffffu, s, o);
    __shared__ float sh[8];
    const int w = tid >> 5, l = tid & 31;
    if (l == 0) sh[w] = s;
    __syncthreads();
    if (tid == 0) {
        float t = 0.f;
#pragma unroll
        for (int i = 0; i < 8; i++) t += sh[i];
        sq[row] = t;
    }
}

// ---------------------------------------------------------------------------
// Online softmax stats per row of length N: max + 1/sum(exp(x-max)).
// ---------------------------------------------------------------------------
__global__ void __launch_bounds__(256)
softmax_stats_kernel(const float* __restrict__ scores,
                     float* __restrict__ mx, float* __restrict__ rs)
{
    const int bh = blockIdx.x;
    const float* x = scores + (size_t)bh * N;
    const int tid = threadIdx.x;

    float m = -3.0e38f, s = 0.f;
    for (int i = tid; i < N; i += 256) {
        float v = x[i];
        if (v > m) { s = s * expf(m - v) + 1.f; m = v; }
        else        s += expf(v - m);
    }
    __shared__ float sm[256], ss[256];
    sm[tid] = m; ss[tid] = s;
    __syncthreads();
    for (int o = 128; o; o >>= 1) {
        if (tid < o) {
            float m2 = sm[tid + o], s2 = ss[tid + o];
            float mm = fmaxf(sm[tid], m2);
            ss[tid] = ss[tid] * expf(sm[tid] - mm) + s2 * expf(m2 - mm);
            sm[tid] = mm;
        }
        __syncthreads();
    }
    if (tid == 0) { mx[bh] = sm[0]; rs[bh] = 1.f / ss[0]; }
}

// ---------------------------------------------------------------------------
// Fused epilogue for one chunk of BCHUNK query rows.
// ---------------------------------------------------------------------------
__global__ void __launch_bounds__(256)
fuse_kernel(const float* __restrict__ dot, const float* __restrict__ scores,
            const float* __restrict__ qsq, const float* __restrict__ ksq,
            const float* __restrict__ mx, const float* __restrict__ rs,
            const float* __restrict__ temp,
            const float* __restrict__ w1, const float* __restrict__ b1,
            const float* __restrict__ w2, const float* __restrict__ b2,
            float* __restrict__ out)
{
    __shared__ float sw1[192], sb1[64], sw2[64];
    const int tid = threadIdx.x;
    if (tid < 192) sw1[tid] = w1[tid];
    if (tid < 64)  { sb1[tid] = b1[tid]; sw2[tid] = w2[tid]; }
    __syncthreads();

    const size_t idx = (size_t)blockIdx.x * 256 + tid;
    const int b = (int)(idx >> 14);        // local b within chunk
    const int n = (int)(idx & (N - 1));

    const float dv = dot[idx];
    const float qs = qsq[b];
    const float ks = ksq[n];
    const float expT = expf(*temp);

    const float cosv = dv * rsqrtf(qs * ks) * expT;
    const float d2   = fmaxf(qs + ks - 2.f * dv, 0.f);
    const float euc  = 1.f / (1.f + sqrtf(d2));

    float lsum = 0.f;
    const int bh0 = b * H;
#pragma unroll
    for (int h = 0; h < H; h++) {
        float sc = scores[((size_t)(bh0 + h) << 14) + n];
        lsum += expf(sc - mx[bh0 + h]) * rs[bh0 + h];
    }
    const float learned = lsum * (1.f / H);

    float acc = b2[0];
#pragma unroll 8
    for (int j = 0; j < 64; j++) {
        float hj = fmaf(cosv, sw1[j],
                   fmaf(euc, sw1[64 + j],
                   fmaf(learned, sw1[128 + j], sb1[j])));
        hj = fmaxf(hj, 0.f);
        acc = fmaf(hj, sw2[j], acc);
    }
    out[idx] = 1.f / (1.f + expf(-acc));
}

// ---------------------------------------------------------------------------
// Host launcher
// ---------------------------------------------------------------------------
extern "C" void kernel_launch(void* const* d_in, const int* in_sizes, int n_in,
                              void* d_out, int out_size)
{
    const float* qf   = (const float*)d_in[0];
    const float* cf   = (const float*)d_in[1];
    const float* temp = (const float*)d_in[2];
    const float* q_w1 = (const float*)d_in[3];
    const float* q_b1 = (const float*)d_in[4];
    const float* q_g  = (const float*)d_in[5];
    const float* q_be = (const float*)d_in[6];
    const float* q_w2 = (const float*)d_in[7];
    const float* q_b2 = (const float*)d_in[8];
    const float* k_w1 = (const float*)d_in[9];
    const float* k_b1 = (const float*)d_in[10];
    const float* k_g  = (const float*)d_in[11];
    const float* k_be = (const float*)d_in[12];
    const float* k_w2 = (const float*)d_in[13];
    const float* k_b2 = (const float*)d_in[14];
    const float* wq   = (const float*)d_in[15];
    const float* bq   = (const float*)d_in[16];
    const float* wk   = (const float*)d_in[17];
    const float* bk   = (const float*)d_in[18];
    const float* f_w1 = (const float*)d_in[19];
    const float* f_b1 = (const float*)d_in[20];
    const float* f_w2 = (const float*)d_in[21];
    const float* f_b2 = (const float*)d_in[22];
    float* out = (float*)d_out;

    char* base;
    cudaGetSymbolAddress((void**)&base, g_arena);
    typedef __half hf;

    float* tmp  = (float*)(base + OFF_TMP);
    float* dot  = (float*)(base + OFF_TMP);      // alias (tmp dead by then)
    hf*  cf_h   = (hf*)(base + OFF_CF_H);
    hf*  cf_l   = (hf*)(base + OFF_CF_L);
    hf*  kh_h   = (hf*)(base + OFF_CF_H);        // alias (cf dead after GEMM1)
    hf*  gk_h   = (hf*)(base + OFF_GK_H);
    hf*  gk_l   = (hf*)(base + OFF_GK_L);
    float* sc   = (float*)(base + OFF_GK_H);     // alias, spans GK_H..GK_L
    hf*  kp_h   = (hf*)(base + OFF_KP_H);
    float* qtmp = (float*)(base + OFF_QTMP);
    hf*  qf_h   = (hf*)(base + OFF_QF_H);
    hf*  qf_l   = (hf*)(base + OFF_QF_L);
    hf*  gq_h   = (hf*)(base + OFF_GQ_H);
    hf*  gq_l   = (hf*)(base + OFF_GQ_L);
    hf*  qp_h   = (hf*)(base + OFF_QP_H);
    hf*  qp_l   = (hf*)(base + OFF_QP_L);
    hf*  qh_h   = (hf*)(base + OFF_QH_H);
    hf*  qh_l   = (hf*)(base + OFF_QH_L);
    float* qsq  = (float*)(base + OFF_QSQ);
    float* ksq  = (float*)(base + OFF_KSQ);
    float* mx   = (float*)(base + OFF_MX);
    float* rs   = (float*)(base + OFF_RS);

    // 6 transposed fp16 weights: 0:k_w1 1:k_w2 2:wk 3:q_w1 4:q_w2 5:wq
    hf* wth[6];
    const float* wsrc[6] = {k_w1, k_w2, wk, q_w1, q_w2, wq};
    for (int i = 0; i < 6; i++)
        wth[i] = (hf*)(base + OFF_W + (size_t)i * 2 * MB);

    cudaFuncSetAttribute(bgemm_kernel<false>,
        cudaFuncAttributeMaxDynamicSharedMemorySize, GEMM_SMEM);
    cudaFuncSetAttribute(bgemm_kernel<true>,
        cudaFuncAttributeMaxDynamicSharedMemorySize, GEMM_SMEM);

    const float inv_sqrt_hd = 0.088388347648318447f; // 1/sqrt(128)

    // --- Prep: weight transposes (hi), input splits ---
    for (int i = 0; i < 6; i++)
        transpose_h_kernel<<<dim3(32, 32), dim3(32, 8)>>>(wsrc[i], wth[i]);
    split_kernel<<<(N * D / 4 + 255) / 256, 256>>>(
        (const float4*)cf, (__half2*)cf_h, (__half2*)cf_l, N * D / 4);
    split_kernel<<<(B * D / 4 + 255) / 256, 256>>>(
        (const float4*)qf, (__half2*)qf_h, (__half2*)qf_l, B * D / 4);

    // --- K-side projection ---
    bgemm_kernel<false><<<dim3(D / GBN, N / GBM), 256, GEMM_SMEM>>>(
        cf_h, cf_l, wth[0], k_b1, tmp, nullptr, nullptr,
        N, D, D, D, D, D, 1.f);
    ln_gelu_split_kernel<<<N, 256>>>(tmp, k_g, k_be, gk_h, gk_l);
    bgemm_kernel<false><<<dim3(D / GBN, N / GBM), 256, GEMM_SMEM>>>(
        gk_h, gk_l, wth[1], k_b2, nullptr, kp_h, nullptr,
        N, D, D, D, D, D, 1.f);
    // kh = kp @ wk + bk: A = kp (hi only; lo term lost is ~u^2, negligible)
    bgemm_kernel<false><<<dim3(D / GBN, N / GBM), 256, GEMM_SMEM>>>(
        kp_h, kp_h, wth[2], bk, nullptr, kh_h, nullptr,
        N, D, D, D, D, D, 0.5f);   // A = kp_h + kp_h => scale 0.5

    // --- Q-side projection ---
    bgemm_kernel<false><<<dim3(D / GBN, B / GBM), 256, GEMM_SMEM>>>(
        qf_h, qf_l, wth[3], q_b1, qtmp, nullptr, nullptr,
        B, D, D, D, D, D, 1.f);
    ln_gelu_split_kernel<<<B, 256>>>(qtmp, q_g, q_be, gq_h, gq_l);
    bgemm_kernel<false><<<dim3(D / GBN, B / GBM), 256, GEMM_SMEM>>>(
        gq_h, gq_l, wth[4], q_b2, nullptr, qp_h, qp_l,
        B, D, D, D, D, D, 1.f);
    bgemm_kernel<false><<<dim3(D / GBN, B / GBM), 256, GEMM_SMEM>>>(
        qp_h, qp_l, wth[5], bq, nullptr, qh_h, qh_l,
        B, D, D, D, D, D, 1.f);

    // --- Row norms ---
    rowsq_hl_kernel<<<B, 256>>>(qp_h, qp_l, qsq);
    rowsq_h_kernel<<<N, 256>>>(kp_h, ksq);

    // --- dot = qp @ kp^T [B,N] (overwrites tmp region) ---
    bgemm_kernel<false><<<dim3(N / GBN, B / GBM), 256, GEMM_SMEM>>>(
        qp_h, qp_l, kp_h, nullptr, dot, nullptr, nullptr,
        B, N, D, D, D, N, 1.f);

    // --- scores + softmax + fusion, chunked over query rows ---
    for (int cb = 0; cb < NCHUNKS; cb++) {
        const hf* qhh_c = qh_h + (size_t)cb * BCHUNK * D;
        const hf* qhl_c = qh_l + (size_t)cb * BCHUNK * D;
        const float* dot_c = dot + (size_t)cb * BCHUNK * N;
        const float* qsq_c = qsq + cb * BCHUNK;
        float* out_c = out + (size_t)cb * BCHUNK * N;

        bgemm_kernel<true><<<dim3(N / GBN, BCHUNK / GBM, H), 256, GEMM_SMEM>>>(
            qhh_c, qhl_c, kh_h, nullptr, sc, nullptr, nullptr,
            BCHUNK, N, HD, D, D, H * N, inv_sqrt_hd);

        softmax_stats_kernel<<<BCHUNK * H, 256>>>(sc, mx, rs);

        fuse_kernel<<<((size_t)BCHUNK * N) / 256, 256>>>(dot_c, sc, qsq_c, ksq,
            mx, rs, temp, f_w1, f_b1, f_w2, f_b2, out_c);
    }
}